// round 9
// baseline (speedup 1.0000x reference)
#include <cuda_runtime.h>

// Lorenz96 RK4, batch x 40 fp32.
// fma.rn.f32x2 packed row pairs (rows r, r+3 of 6-row warp windows),
// 10 threads per row-pair, halos via 64-bit shuffles.
// Prefetch-distance-1 pipeline, ITERS=8, guard-free interior fast path.

#define N_STATE 40
#define TPB 256
#define WARPS_PER_BLOCK (TPB / 32)
#define ROWS_PER_WARP 6
#define ITERS 8
#define ROWS_PER_BLOCK_TOTAL (WARPS_PER_BLOCK * ROWS_PER_WARP * ITERS)  // 384

typedef unsigned long long ull;

__device__ __forceinline__ ull pack2(float lo, float hi) {
    ull r;
    asm("mov.b64 %0, {%1, %2};" : "=l"(r) : "f"(lo), "f"(hi));
    return r;
}
__device__ __forceinline__ void unpack2(ull v, float& lo, float& hi) {
    asm("mov.b64 {%0, %1}, %2;" : "=f"(lo), "=f"(hi) : "l"(v));
}
__device__ __forceinline__ ull fma2(ull a, ull b, ull c) {
    ull d;
    asm("fma.rn.f32x2 %0, %1, %2, %3;" : "=l"(d) : "l"(a), "l"(b), "l"(c));
    return d;
}

#define NEG1_2 0xBF800000BF800000ULL   // (-1, -1)
#define ONE_2  0x3F8000003F800000ULL   // ( 1,  1)
#define TWO_2  0x4000000040000000ULL   // ( 2,  2)
#define F_2    0x4100000041000000ULL   // ( 8,  8)  FORCE

template <bool FIRST, bool HAS_NEXT>
__device__ __forceinline__ void stage(const ull* __restrict__ y,
                                      ull* __restrict__ acc,
                                      const ull* __restrict__ x,
                                      ull* __restrict__ yn,
                                      ull W2, ull C2,
                                      unsigned mask, int left, int right) {
    const ull hL2 = __shfl_sync(mask, y[2], left);   // i-2 at e=0
    const ull hL3 = __shfl_sync(mask, y[3], left);   // i-1 at e=0, i-2 at e=1
    const ull hR0 = __shfl_sync(mask, y[0], right);  // i+1 at e=3

    const ull yp1[4] = { y[1], y[2], y[3], hR0 };
    const ull ym1[4] = { hL3,  y[0], y[1], y[2] };
    const ull ym2[4] = { hL2,  hL3,  y[0], y[1] };

#pragma unroll
    for (int e = 0; e < 4; e++) {
        const ull d = fma2(ym2[e], NEG1_2, yp1[e]);   // y_{i+1} - y_{i-2}
        const ull t = fma2(y[e],   NEG1_2, F_2);      // F - y_i
        const ull k = fma2(d, ym1[e], t);
        if (FIRST)
            acc[e] = k;
        else
            acc[e] = fma2(k, W2, acc[e]);
        if (HAS_NEXT)
            yn[e] = fma2(k, C2, x[e]);
    }
}

__device__ __forceinline__ void compute_window(const float4& va, const float4& vb,
                                               float4& oa, float4& ob,
                                               ull hdt2, ull dt2, ull sdt2,
                                               unsigned mask, int left, int right) {
    ull x[4] = { pack2(va.x, vb.x), pack2(va.y, vb.y),
                 pack2(va.z, vb.z), pack2(va.w, vb.w) };
    ull acc[4], ya[4], yb[4];

    stage<true,  true >(x,  acc, x, ya, ONE_2, hdt2, mask, left, right);
    stage<false, true >(ya, acc, x, yb, TWO_2, hdt2, mask, left, right);
    stage<false, true >(yb, acc, x, ya, TWO_2, dt2,  mask, left, right);
    stage<false, false>(ya, acc, x, yb, ONE_2, dt2,  mask, left, right);

    unpack2(fma2(acc[0], sdt2, x[0]), oa.x, ob.x);
    unpack2(fma2(acc[1], sdt2, x[1]), oa.y, ob.y);
    unpack2(fma2(acc[2], sdt2, x[2]), oa.z, ob.z);
    unpack2(fma2(acc[3], sdt2, x[3]), oa.w, ob.w);
}

__global__ __launch_bounds__(TPB, 4)
void lorenz96_rk4_kernel(const float4* __restrict__ x0,
                         const float* __restrict__ dt_ptr,
                         float4* __restrict__ out,
                         int batch) {
    const int lane = threadIdx.x & 31;
    if (lane >= 30) return;                 // lanes 30,31 idle (in no shfl mask)

    const int g = (lane >= 20) ? 2 : (lane >= 10 ? 1 : 0);  // row-pair group
    const int t = lane - g * 10;                            // element chunk

    const int warp = blockIdx.x * WARPS_PER_BLOCK + (threadIdx.x >> 5);
    const int row0 = warp * (ROWS_PER_WARP * ITERS) + g;

    const unsigned mask = 0x3FFu << (g * 10);
    const int base = g * 10;
    const int left  = (t == 0) ? base + 9 : lane - 1;
    const int right = (t == 9) ? base     : lane + 1;

    const float dt = __ldg(dt_ptr);
    const ull dt2  = pack2(dt, dt);
    const ull hdt2 = pack2(0.5f * dt, 0.5f * dt);
    const float sdt = dt * (1.0f / 6.0f);
    const ull sdt2 = pack2(sdt, sdt);

    const float4* __restrict__ pin  = x0  + (row0 * 10 + t);
    float4*       __restrict__ pout = out + (row0 * 10 + t);

    // Interior fast path: the whole warp-chunk fits (true for all full blocks).
    if (row0 - g + ROWS_PER_WARP * ITERS <= batch) {
        float4 a0 = pin[0];
        float4 b0 = pin[30];

#pragma unroll
        for (int i = 0; i < ITERS; i++) {
            float4 a1, b1;
            if (i + 1 < ITERS) {               // unconditional loads in unrolled body
                a1 = pin[(i + 1) * 60];
                b1 = pin[(i + 1) * 60 + 30];
            }

            float4 oa, ob;
            compute_window(a0, b0, oa, ob, hdt2, dt2, sdt2, mask, left, right);
            pout[i * 60]      = oa;
            pout[i * 60 + 30] = ob;

            a0 = a1; b0 = b1;
        }
        return;
    }

    // ---- Tail path (last block only): fully guarded ----
    for (int i = 0; i < ITERS; i++) {
        const int r = row0 + i * ROWS_PER_WARP;
        if (r >= batch) break;
        const bool bOK = (r + 3 < batch);
        const float4 va = pin[i * 60];
        const float4 vb = bOK ? pin[i * 60 + 30] : va;

        float4 oa, ob;
        compute_window(va, vb, oa, ob, hdt2, dt2, sdt2, mask, left, right);
        pout[i * 60] = oa;
        if (bOK) pout[i * 60 + 30] = ob;
    }
}

extern "C" void kernel_launch(void* const* d_in, const int* in_sizes, int n_in,
                              void* d_out, int out_size) {
    const float4* x0 = (const float4*)d_in[0];
    // d_in[1] is t (unused, autonomous system)
    const float* dt = (const float*)d_in[2];
    float4* out = (float4*)d_out;

    const int batch = in_sizes[0] / N_STATE;
    const int blocks = (batch + ROWS_PER_BLOCK_TOTAL - 1) / ROWS_PER_BLOCK_TOTAL;
    lorenz96_rk4_kernel<<<blocks, TPB>>>(x0, dt, out, batch);
}

// round 10
// speedup vs baseline: 1.0589x; 1.0589x over previous
#include <cuda_runtime.h>

// Lorenz96 RK4, batch x 40 fp32.
// Persistent grid-stride kernel: 592 CTAs (1 full wave at 4 CTAs/SM).
// fma.rn.f32x2 packed row pairs (rows r, r+3 per 6-row window),
// 10 threads per row-pair, halos via 64-bit shuffles.
// Prefetch distance 1 carried across grid-stride iterations.

#define N_STATE 40
#define TPB 256
#define WARPS_PER_BLOCK (TPB / 32)
#define ROWS_PER_WARP 6
#define MAX_CTAS 592            // 148 SMs x 4 CTAs/SM

typedef unsigned long long ull;

__device__ __forceinline__ ull pack2(float lo, float hi) {
    ull r;
    asm("mov.b64 %0, {%1, %2};" : "=l"(r) : "f"(lo), "f"(hi));
    return r;
}
__device__ __forceinline__ void unpack2(ull v, float& lo, float& hi) {
    asm("mov.b64 {%0, %1}, %2;" : "=f"(lo), "=f"(hi) : "l"(v));
}
__device__ __forceinline__ ull fma2(ull a, ull b, ull c) {
    ull d;
    asm("fma.rn.f32x2 %0, %1, %2, %3;" : "=l"(d) : "l"(a), "l"(b), "l"(c));
    return d;
}

#define NEG1_2 0xBF800000BF800000ULL   // (-1, -1)
#define ONE_2  0x3F8000003F800000ULL   // ( 1,  1)
#define TWO_2  0x4000000040000000ULL   // ( 2,  2)
#define F_2    0x4100000041000000ULL   // ( 8,  8)  FORCE

template <bool FIRST, bool HAS_NEXT>
__device__ __forceinline__ void stage(const ull* __restrict__ y,
                                      ull* __restrict__ acc,
                                      const ull* __restrict__ x,
                                      ull* __restrict__ yn,
                                      ull W2, ull C2,
                                      unsigned mask, int left, int right) {
    const ull hL2 = __shfl_sync(mask, y[2], left);   // i-2 at e=0
    const ull hL3 = __shfl_sync(mask, y[3], left);   // i-1 at e=0, i-2 at e=1
    const ull hR0 = __shfl_sync(mask, y[0], right);  // i+1 at e=3

    const ull yp1[4] = { y[1], y[2], y[3], hR0 };
    const ull ym1[4] = { hL3,  y[0], y[1], y[2] };
    const ull ym2[4] = { hL2,  hL3,  y[0], y[1] };

#pragma unroll
    for (int e = 0; e < 4; e++) {
        const ull d = fma2(ym2[e], NEG1_2, yp1[e]);   // y_{i+1} - y_{i-2}
        const ull t = fma2(y[e],   NEG1_2, F_2);      // F - y_i
        const ull k = fma2(d, ym1[e], t);
        if (FIRST)
            acc[e] = k;
        else
            acc[e] = fma2(k, W2, acc[e]);
        if (HAS_NEXT)
            yn[e] = fma2(k, C2, x[e]);
    }
}

__global__ __launch_bounds__(TPB, 4)
void lorenz96_rk4_kernel(const float4* __restrict__ x0,
                         const float* __restrict__ dt_ptr,
                         float4* __restrict__ out,
                         int batch) {
    const int lane = threadIdx.x & 31;
    if (lane >= 30) return;                 // lanes 30,31 idle (in no shfl mask)

    const int g = (lane >= 20) ? 2 : (lane >= 10 ? 1 : 0);  // row-pair group
    const int t = lane - g * 10;                            // element chunk

    const unsigned mask = 0x3FFu << (g * 10);
    const int base = g * 10;
    const int left  = (t == 0) ? base + 9 : lane - 1;
    const int right = (t == 9) ? base     : lane + 1;

    const float dt = __ldg(dt_ptr);
    const ull dt2  = pack2(dt, dt);
    const ull hdt2 = pack2(0.5f * dt, 0.5f * dt);
    const float sdt = dt * (1.0f / 6.0f);
    const ull sdt2 = pack2(sdt, sdt);

    const int warp = blockIdx.x * WARPS_PER_BLOCK + (threadIdx.x >> 5);
    const int strideRows = gridDim.x * WARPS_PER_BLOCK * ROWS_PER_WARP;
    const int strideVec = strideRows * 10;

    int rowA = warp * ROWS_PER_WARP + g;          // pair = (rowA, rowA+3)
    bool aOK = (rowA < batch);
    if (!aOK) return;                              // group-uniform
    bool bOK = (rowA + 3 < batch);

    const float4* __restrict__ pin  = x0  + (rowA * 10 + t);
    float4*       __restrict__ pout = out + (rowA * 10 + t);

    float4 va = pin[0];
    float4 vb;
    if (bOK) vb = pin[30];

    while (aOK) {
        // ---- Prefetch next grid-stride window ----
        const int rn = rowA + strideRows;
        const bool naOK = (rn < batch);
        const bool nbOK = (rn + 3 < batch);
        float4 na, nb;
        if (naOK) na = pin[strideVec];
        if (nbOK) nb = pin[strideVec + 30];

        // ---- Compute current window ----
        const float4 vbs = bOK ? vb : va;
        ull x[4] = { pack2(va.x, vbs.x), pack2(va.y, vbs.y),
                     pack2(va.z, vbs.z), pack2(va.w, vbs.w) };
        ull acc[4], ya[4], yb[4];

        stage<true,  true >(x,  acc, x, ya, ONE_2, hdt2, mask, left, right);
        stage<false, true >(ya, acc, x, yb, TWO_2, hdt2, mask, left, right);
        stage<false, true >(yb, acc, x, ya, TWO_2, dt2,  mask, left, right);
        stage<false, false>(ya, acc, x, yb, ONE_2, dt2,  mask, left, right);

        float4 oa, ob;
        unpack2(fma2(acc[0], sdt2, x[0]), oa.x, ob.x);
        unpack2(fma2(acc[1], sdt2, x[1]), oa.y, ob.y);
        unpack2(fma2(acc[2], sdt2, x[2]), oa.z, ob.z);
        unpack2(fma2(acc[3], sdt2, x[3]), oa.w, ob.w);

        pout[0] = oa;
        if (bOK) pout[30] = ob;

        // ---- Rotate ----
        va = na; vb = nb;
        aOK = naOK; bOK = nbOK;
        rowA = rn;
        pin += strideVec; pout += strideVec;
    }
}

extern "C" void kernel_launch(void* const* d_in, const int* in_sizes, int n_in,
                              void* d_out, int out_size) {
    const float4* x0 = (const float4*)d_in[0];
    // d_in[1] is t (unused, autonomous system)
    const float* dt = (const float*)d_in[2];
    float4* out = (float4*)d_out;

    const int batch = in_sizes[0] / N_STATE;
    const int windows = (batch + ROWS_PER_WARP - 1) / ROWS_PER_WARP;
    const int blocksNeeded = (windows + WARPS_PER_BLOCK - 1) / WARPS_PER_BLOCK;
    const int blocks = blocksNeeded < MAX_CTAS ? blocksNeeded : MAX_CTAS;
    lorenz96_rk4_kernel<<<blocks, TPB>>>(x0, dt, out, batch);
}